// round 1
// baseline (speedup 1.0000x reference)
#include <cuda_runtime.h>

// involution: B=4, C=256, G=16, K=7, S=1, P=3, R=4, H=W=56
#define BB   4
#define CC   256
#define GG   16
#define CPG  16      // C/G
#define KF   7
#define PAD  3
#define HH   56
#define WW   56
#define CR   64      // C/R
#define KK   49      // K*K
#define KKG  784     // K*K*G
#define TW   28      // pixel tile width (half a row)
#define TQ   (TW/4)  // 7 float4 quads per tile
#define NTHREADS 512

// smem: xs[C][TW] + hs[CR][TW] + ks[KKG][TW]  = (7168+1792+21952)*4 = 123648 B
#define SMEM_FLOATS (CC*TW + CR*TW + KKG*TW)

__global__ __launch_bounds__(NTHREADS, 1)
void inv_fused_kernel(const float* __restrict__ x,
                      const float* __restrict__ rw,   // [CR][C]
                      const float* __restrict__ rb,   // [CR]
                      const float* __restrict__ sw,   // [KKG][CR]
                      const float* __restrict__ sb,   // [KKG]
                      float* __restrict__ out)
{
    extern __shared__ float smem[];
    float* xs = smem;                 // [CC][TW]
    float* hs = xs + CC * TW;         // [CR][TW]
    float* ks = hs + CR * TW;         // [KKG][TW]
    float4* xs4 = (float4*)xs;
    float4* hs4 = (float4*)hs;
    float4* ks4 = (float4*)ks;

    const int x0  = blockIdx.x * TW;      // 0 or 28
    const int y   = blockIdx.y;           // 0..55
    const int b   = blockIdx.z;           // 0..3
    const int tid = threadIdx.x;

    // ---------------- Phase 1: load x slice [C][TW] (float4, coalesced) ----
    {
        const float4* xg4 = (const float4*)(x + ((size_t)(b * CC) * HH + y) * WW + x0);
        const int cstride4 = (HH * WW) / 4;   // float4 stride between channels
        #pragma unroll
        for (int idx = tid; idx < CC * TQ; idx += NTHREADS) {
            int c = idx / TQ;
            int q = idx - c * TQ;
            xs4[c * TQ + q] = xg4[(size_t)c * cstride4 + q];
        }
    }
    __syncthreads();

    // ---------------- Phase 2: h[o][px] = sum_c rw[o][c]*xs[c][px] + rb[o] --
    // tasks: 64 o * 7 px-quads = 448 (<512 threads, one task each)
    if (tid < CR * TQ) {
        int o  = tid / TQ;
        int pq = tid - o * TQ;
        float4 acc = make_float4(0.f, 0.f, 0.f, 0.f);
        const float4* w4 = (const float4*)(rw + o * CC);
        #pragma unroll 8
        for (int k = 0; k < CC; k += 4) {
            float4 w  = w4[k >> 2];
            float4 v0 = xs4[(k + 0) * TQ + pq];
            float4 v1 = xs4[(k + 1) * TQ + pq];
            float4 v2 = xs4[(k + 2) * TQ + pq];
            float4 v3 = xs4[(k + 3) * TQ + pq];
            acc.x += w.x * v0.x + w.y * v1.x + w.z * v2.x + w.w * v3.x;
            acc.y += w.x * v0.y + w.y * v1.y + w.z * v2.y + w.w * v3.y;
            acc.z += w.x * v0.z + w.y * v1.z + w.z * v2.z + w.w * v3.z;
            acc.w += w.x * v0.w + w.y * v1.w + w.z * v2.w + w.w * v3.w;
        }
        float bias = rb[o];
        acc.x += bias; acc.y += bias; acc.z += bias; acc.w += bias;
        hs4[o * TQ + pq] = acc;
    }
    __syncthreads();

    // ---------------- Phase 3: kern[o][px] = sum_k sw[o][k]*h[k][px] + sb[o]
    // register tile 4o x 4px; tasks: 196 o-quads * 7 px-quads = 1372
    for (int t = tid; t < (KKG / 4) * TQ; t += NTHREADS) {
        int oq = t / TQ;
        int pq = t - oq * TQ;
        int o  = oq * 4;
        float4 a0 = make_float4(0.f, 0.f, 0.f, 0.f);
        float4 a1 = a0, a2 = a0, a3 = a0;
        const float4* s0 = (const float4*)(sw + (o + 0) * CR);
        const float4* s1 = (const float4*)(sw + (o + 1) * CR);
        const float4* s2 = (const float4*)(sw + (o + 2) * CR);
        const float4* s3 = (const float4*)(sw + (o + 3) * CR);
        #pragma unroll
        for (int k = 0; k < CR; k += 4) {
            float4 w0 = s0[k >> 2];
            float4 w1 = s1[k >> 2];
            float4 w2 = s2[k >> 2];
            float4 w3 = s3[k >> 2];
            float4 v0 = hs4[(k + 0) * TQ + pq];
            float4 v1 = hs4[(k + 1) * TQ + pq];
            float4 v2 = hs4[(k + 2) * TQ + pq];
            float4 v3 = hs4[(k + 3) * TQ + pq];

            a0.x += w0.x * v0.x + w0.y * v1.x + w0.z * v2.x + w0.w * v3.x;
            a0.y += w0.x * v0.y + w0.y * v1.y + w0.z * v2.y + w0.w * v3.y;
            a0.z += w0.x * v0.z + w0.y * v1.z + w0.z * v2.z + w0.w * v3.z;
            a0.w += w0.x * v0.w + w0.y * v1.w + w0.z * v2.w + w0.w * v3.w;

            a1.x += w1.x * v0.x + w1.y * v1.x + w1.z * v2.x + w1.w * v3.x;
            a1.y += w1.x * v0.y + w1.y * v1.y + w1.z * v2.y + w1.w * v3.y;
            a1.z += w1.x * v0.z + w1.y * v1.z + w1.z * v2.z + w1.w * v3.z;
            a1.w += w1.x * v0.w + w1.y * v1.w + w1.z * v2.w + w1.w * v3.w;

            a2.x += w2.x * v0.x + w2.y * v1.x + w2.z * v2.x + w2.w * v3.x;
            a2.y += w2.x * v0.y + w2.y * v1.y + w2.z * v2.y + w2.w * v3.y;
            a2.z += w2.x * v0.z + w2.y * v1.z + w2.z * v2.z + w2.w * v3.z;
            a2.w += w2.x * v0.w + w2.y * v1.w + w2.z * v2.w + w2.w * v3.w;

            a3.x += w3.x * v0.x + w3.y * v1.x + w3.z * v2.x + w3.w * v3.x;
            a3.y += w3.x * v0.y + w3.y * v1.y + w3.z * v2.y + w3.w * v3.y;
            a3.z += w3.x * v0.z + w3.y * v1.z + w3.z * v2.z + w3.w * v3.z;
            a3.w += w3.x * v0.w + w3.y * v1.w + w3.z * v2.w + w3.w * v3.w;
        }
        float b0 = sb[o + 0], b1 = sb[o + 1], b2 = sb[o + 2], b3 = sb[o + 3];
        a0.x += b0; a0.y += b0; a0.z += b0; a0.w += b0;
        a1.x += b1; a1.y += b1; a1.z += b1; a1.w += b1;
        a2.x += b2; a2.y += b2; a2.z += b2; a2.w += b2;
        a3.x += b3; a3.y += b3; a3.z += b3; a3.w += b3;
        ks4[(o + 0) * TQ + pq] = a0;
        ks4[(o + 1) * TQ + pq] = a1;
        ks4[(o + 2) * TQ + pq] = a2;
        ks4[(o + 3) * TQ + pq] = a3;
    }
    __syncthreads();

    // ---------------- Phase 4: involution apply ----------------------------
    // warp w handles group g=w (16 warps = 16 groups); lanes 0..27 = px
    {
        const int w    = tid >> 5;
        const int lane = tid & 31;
        if (lane < TW) {
            const int px = lane;
            const int g  = w;
            const float* kb = ks + g * KK * TW;
            #pragma unroll 1
            for (int ci = 0; ci < CPG; ci++) {
                const int c = g * CPG + ci;
                const float* xrow = x + (size_t)(b * CC + c) * HH * WW;
                float acc = 0.f;
                #pragma unroll
                for (int kh = 0; kh < KF; kh++) {
                    const int yy = y + kh - PAD;
                    const bool yok = ((unsigned)yy < HH);
                    #pragma unroll
                    for (int kw = 0; kw < KF; kw++) {
                        const int xx = x0 + px + kw - PAD;
                        float v = 0.f;
                        if (yok && ((unsigned)xx < WW))
                            v = __ldg(xrow + yy * WW + xx);
                        acc += kb[(kh * KF + kw) * TW + px] * v;
                    }
                }
                out[((size_t)(b * CC + c) * HH + y) * WW + x0 + px] = acc;
            }
        }
    }
}

extern "C" void kernel_launch(void* const* d_in, const int* in_sizes, int n_in,
                              void* d_out, int out_size)
{
    const float* x  = (const float*)d_in[0];  // (4,256,56,56)
    const float* rw = (const float*)d_in[1];  // (64,256)
    const float* rb = (const float*)d_in[2];  // (64,)
    const float* sw = (const float*)d_in[3];  // (784,64)
    const float* sb = (const float*)d_in[4];  // (784,)
    float* out = (float*)d_out;               // (4,256,56,56)

    const int smem_bytes = SMEM_FLOATS * (int)sizeof(float);  // 123648
    cudaFuncSetAttribute(inv_fused_kernel,
                         cudaFuncAttributeMaxDynamicSharedMemorySize, smem_bytes);

    dim3 grid(WW / TW, HH, BB);   // (2, 56, 4) = 448 blocks
    inv_fused_kernel<<<grid, NTHREADS, smem_bytes>>>(x, rw, rb, sw, sb, out);
}

// round 2
// speedup vs baseline: 1.1271x; 1.1271x over previous
#include <cuda_runtime.h>

// involution: B=4, C=256, G=16, K=7, S=1, P=3, R=4, H=W=56
#define BB   4
#define CC   256
#define GG   16
#define CPG  16      // C/G
#define KF   7
#define PAD  3
#define HH   56
#define WW   56
#define CR   64      // C/R
#define KK   49      // K*K
#define KKG  784     // K*K*G
#define TW   28      // pixel tile width (half a row)
#define TQ   (TW/4)  // 7 float4 quads per tile
#define NTHREADS 512

// padded x window: 128 channels (half the block's channels) x 7 rows x 36 cols
#define XWC   128            // channels staged per half (8 per group)
#define XWW   36             // padded window width (cols x0-4 .. x0+31)
#define XW_FLOATS (XWC * KF * XWW)          // 32256
#define KS_FLOATS (KKG * TW)                // 21952
#define SMEM_FLOATS (KS_FLOATS + XW_FLOATS) // 54208 floats = 216832 B

__global__ __launch_bounds__(NTHREADS, 1)
void inv_fused_kernel(const float* __restrict__ x,
                      const float* __restrict__ rw,   // [CR][C]
                      const float* __restrict__ rb,   // [CR]
                      const float* __restrict__ sw,   // [KKG][CR]
                      const float* __restrict__ sb,   // [KKG]
                      float* __restrict__ out)
{
    extern __shared__ float smem[];
    float* ks = smem;                  // [KKG][TW]   (87.8 KB, lives all kernel)
    float* xw = smem + KS_FLOATS;      // [XWC][7][36] (129 KB, phase 4 only)
    // xs/hs live inside the xw region (dead before xw is filled)
    float* xs = xw;                    // [CC][TW]
    float* hs = xw + CC * TW;          // [CR][TW]
    float4* xs4 = (float4*)xs;
    float4* hs4 = (float4*)hs;
    float4* ks4 = (float4*)ks;

    const int x0  = blockIdx.x * TW;      // 0 or 28
    const int y   = blockIdx.y;           // 0..55
    const int b   = blockIdx.z;           // 0..3
    const int tid = threadIdx.x;

    // ---------------- Phase 1: load x slice [C][TW] (row y, float4) --------
    {
        const float4* xg4 = (const float4*)(x + ((size_t)(b * CC) * HH + y) * WW + x0);
        const int cstride4 = (HH * WW) / 4;
        #pragma unroll
        for (int idx = tid; idx < CC * TQ; idx += NTHREADS) {
            int c = idx / TQ;
            int q = idx - c * TQ;
            xs4[c * TQ + q] = xg4[(size_t)c * cstride4 + q];
        }
    }
    __syncthreads();

    // ---------------- Phase 2: h[o][px] = sum_c rw[o][c]*xs[c][px] + rb[o] --
    if (tid < CR * TQ) {
        int o  = tid / TQ;
        int pq = tid - o * TQ;
        float4 acc = make_float4(0.f, 0.f, 0.f, 0.f);
        const float4* w4 = (const float4*)(rw + o * CC);
        #pragma unroll 8
        for (int k = 0; k < CC; k += 4) {
            float4 w  = w4[k >> 2];
            float4 v0 = xs4[(k + 0) * TQ + pq];
            float4 v1 = xs4[(k + 1) * TQ + pq];
            float4 v2 = xs4[(k + 2) * TQ + pq];
            float4 v3 = xs4[(k + 3) * TQ + pq];
            acc.x += w.x * v0.x + w.y * v1.x + w.z * v2.x + w.w * v3.x;
            acc.y += w.x * v0.y + w.y * v1.y + w.z * v2.y + w.w * v3.y;
            acc.z += w.x * v0.z + w.y * v1.z + w.z * v2.z + w.w * v3.z;
            acc.w += w.x * v0.w + w.y * v1.w + w.z * v2.w + w.w * v3.w;
        }
        float bias = rb[o];
        acc.x += bias; acc.y += bias; acc.z += bias; acc.w += bias;
        hs4[o * TQ + pq] = acc;
    }
    __syncthreads();

    // ---------------- Phase 3: kern[o][px] = sum_k sw[o][k]*h[k][px] + sb[o]
    for (int t = tid; t < (KKG / 4) * TQ; t += NTHREADS) {
        int oq = t / TQ;
        int pq = t - oq * TQ;
        int o  = oq * 4;
        float4 a0 = make_float4(0.f, 0.f, 0.f, 0.f);
        float4 a1 = a0, a2 = a0, a3 = a0;
        const float4* s0 = (const float4*)(sw + (o + 0) * CR);
        const float4* s1 = (const float4*)(sw + (o + 1) * CR);
        const float4* s2 = (const float4*)(sw + (o + 2) * CR);
        const float4* s3 = (const float4*)(sw + (o + 3) * CR);
        #pragma unroll
        for (int k = 0; k < CR; k += 4) {
            float4 w0 = s0[k >> 2];
            float4 w1 = s1[k >> 2];
            float4 w2 = s2[k >> 2];
            float4 w3 = s3[k >> 2];
            float4 v0 = hs4[(k + 0) * TQ + pq];
            float4 v1 = hs4[(k + 1) * TQ + pq];
            float4 v2 = hs4[(k + 2) * TQ + pq];
            float4 v3 = hs4[(k + 3) * TQ + pq];

            a0.x += w0.x * v0.x + w0.y * v1.x + w0.z * v2.x + w0.w * v3.x;
            a0.y += w0.x * v0.y + w0.y * v1.y + w0.z * v2.y + w0.w * v3.y;
            a0.z += w0.x * v0.z + w0.y * v1.z + w0.z * v2.z + w0.w * v3.z;
            a0.w += w0.x * v0.w + w0.y * v1.w + w0.z * v2.w + w0.w * v3.w;

            a1.x += w1.x * v0.x + w1.y * v1.x + w1.z * v2.x + w1.w * v3.x;
            a1.y += w1.x * v0.y + w1.y * v1.y + w1.z * v2.y + w1.w * v3.y;
            a1.z += w1.x * v0.z + w1.y * v1.z + w1.z * v2.z + w1.w * v3.z;
            a1.w += w1.x * v0.w + w1.y * v1.w + w1.z * v2.w + w1.w * v3.w;

            a2.x += w2.x * v0.x + w2.y * v1.x + w2.z * v2.x + w2.w * v3.x;
            a2.y += w2.x * v0.y + w2.y * v1.y + w2.z * v2.y + w2.w * v3.y;
            a2.z += w2.x * v0.z + w2.y * v1.z + w2.z * v2.z + w2.w * v3.z;
            a2.w += w2.x * v0.w + w2.y * v1.w + w2.z * v2.w + w2.w * v3.w;

            a3.x += w3.x * v0.x + w3.y * v1.x + w3.z * v2.x + w3.w * v3.x;
            a3.y += w3.x * v0.y + w3.y * v1.y + w3.z * v2.y + w3.w * v3.y;
            a3.z += w3.x * v0.z + w3.y * v1.z + w3.z * v2.z + w3.w * v3.z;
            a3.w += w3.x * v0.w + w3.y * v1.w + w3.z * v2.w + w3.w * v3.w;
        }
        float b0 = sb[o + 0], b1 = sb[o + 1], b2 = sb[o + 2], b3 = sb[o + 3];
        a0.x += b0; a0.y += b0; a0.z += b0; a0.w += b0;
        a1.x += b1; a1.y += b1; a1.z += b1; a1.w += b1;
        a2.x += b2; a2.y += b2; a2.z += b2; a2.w += b2;
        a3.x += b3; a3.y += b3; a3.z += b3; a3.w += b3;
        ks4[(o + 0) * TQ + pq] = a0;
        ks4[(o + 1) * TQ + pq] = a1;
        ks4[(o + 2) * TQ + pq] = a2;
        ks4[(o + 3) * TQ + pq] = a3;
    }
    __syncthreads();

    // ---------------- Phase 4: involution apply ----------------------------
    // warp g (=tid>>5) handles group g; lane = px (0..27).
    // Kernel values held in 49 registers per lane, reused across 16 channels.
    // x window staged zero-padded in smem in two 128-channel halves:
    //   xw[c_local][r][off] = x[c][y+r-3][x0-4+off]  (0 outside image)
    const int warp = tid >> 5;
    const int lane = tid & 31;

    float kr[KK];
    if (lane < TW) {
        const float* kb = ks + warp * KK * TW + lane;
        #pragma unroll
        for (int t = 0; t < KK; t++) kr[t] = kb[t * TW];
    }

    #pragma unroll
    for (int half = 0; half < 2; half++) {
        // ---- fill xw: 128 channels x 7 rows x 9 quads = 8064 float4 -------
        {
            float4* xw4 = (float4*)xw;
            const float4 zero4 = make_float4(0.f, 0.f, 0.f, 0.f);
            for (int idx = tid; idx < XWC * KF * (XWW / 4); idx += NTHREADS) {
                int cl = idx / (KF * (XWW / 4));          // 0..127
                int rq = idx - cl * (KF * (XWW / 4));
                int r  = rq / (XWW / 4);                  // 0..6
                int q  = rq - r * (XWW / 4);              // 0..8
                int g  = cl >> 3;
                int ci = cl & 7;
                int c  = g * CPG + half * 8 + ci;
                int yy = y + r - PAD;
                int col0 = x0 - 4 + q * 4;                // multiple of 4
                float4 v = zero4;
                if ((unsigned)yy < HH && (unsigned)col0 < WW)  // full quad valid
                    v = *(const float4*)(x + ((size_t)(b * CC + c) * HH + yy) * WW + col0);
                xw4[idx] = v;
            }
        }
        __syncthreads();

        // ---- apply: each lane: 8 channels x 49 taps (pure LDS + FFMA) -----
        if (lane < TW) {
            const int g = warp;
            #pragma unroll 1
            for (int ci = 0; ci < 8; ci++) {
                const float* wrow = xw + ((g * 8 + ci) * KF) * XWW + lane + 1;
                float a0 = 0.f, a1 = 0.f;
                #pragma unroll
                for (int r = 0; r < KF; r++) {
                    #pragma unroll
                    for (int kw = 0; kw < KF; kw++) {
                        float v = wrow[r * XWW + kw];
                        if (kw & 1) a1 += kr[r * KF + kw] * v;
                        else        a0 += kr[r * KF + kw] * v;
                    }
                }
                const int c = g * CPG + half * 8 + ci;
                out[((size_t)(b * CC + c) * HH + y) * WW + x0 + lane] = a0 + a1;
            }
        }
        __syncthreads();   // WAR: half1 fill overwrites xw
    }
}

extern "C" void kernel_launch(void* const* d_in, const int* in_sizes, int n_in,
                              void* d_out, int out_size)
{
    const float* x  = (const float*)d_in[0];  // (4,256,56,56)
    const float* rw = (const float*)d_in[1];  // (64,256)
    const float* rb = (const float*)d_in[2];  // (64,)
    const float* sw = (const float*)d_in[3];  // (784,64)
    const float* sb = (const float*)d_in[4];  // (784,)
    float* out = (float*)d_out;               // (4,256,56,56)

    const int smem_bytes = SMEM_FLOATS * (int)sizeof(float);  // 216832
    cudaFuncSetAttribute(inv_fused_kernel,
                         cudaFuncAttributeMaxDynamicSharedMemorySize, smem_bytes);

    dim3 grid(WW / TW, HH, BB);   // (2, 56, 4) = 448 blocks
    inv_fused_kernel<<<grid, NTHREADS, smem_bytes>>>(x, rw, rb, sw, sb, out);
}

// round 3
// speedup vs baseline: 1.2537x; 1.1123x over previous
#include <cuda_runtime.h>

// involution: B=4, C=256, G=16, K=7, S=1, P=3, R=4, H=W=56
#define BB   4
#define CC   256
#define GG   16
#define CPG  16      // C/G
#define KF   7
#define PAD  3
#define HH   56
#define WW   56
#define CR   64      // C/R
#define KK   49      // K*K
#define KKG  784     // K*K*G
#define TW   28      // pixel tile width (half a row)
#define TQ   (TW/4)
#define NTHREADS 512

#define HSTR  76              // hs_t row stride in floats (conflict-free, 4-aligned)
#define HSTR4 (HSTR/4)        // 19

// padded x window: 128 channels x 7 rows x 36 cols
#define XWC   128
#define XWW   36
#define XW_FLOATS (XWC * KF * XWW)          // 32256
#define KS_FLOATS (KKG * TW)                // 21952
#define SMEM_FLOATS (KS_FLOATS + XW_FLOATS) // 54208 floats = 216832 B

__global__ __launch_bounds__(NTHREADS, 1)
void inv_fused_kernel(const float* __restrict__ x,
                      const float* __restrict__ rw,   // [CR][C]
                      const float* __restrict__ rb,   // [CR]
                      const float* __restrict__ sw,   // [KKG][CR]
                      const float* __restrict__ sb,   // [KKG]
                      float* __restrict__ out)
{
    extern __shared__ float smem[];
    float* ks = smem;                   // [KKG][TW]   87.8 KB, persists
    float* xw = smem + KS_FLOATS;       // [XWC][7][36] phase-4 window
    float* xs = xw;                     // [CC][TW]  (dead before xw fill)
    float* hs = xw + CC * TW;           // hs_t [TW][HSTR]  (dead before xw fill)
    float4* xs4 = (float4*)xs;
    float4* hs4 = (float4*)hs;
    float4* ks4 = (float4*)ks;

    const int x0   = blockIdx.x * TW;
    const int y    = blockIdx.y;
    const int b    = blockIdx.z;
    const int tid  = threadIdx.x;
    const int warp = tid >> 5;
    const int lane = tid & 31;

    // ---------------- Phase 1: load x slice [C][TW] (row y, float4) --------
    {
        const float4* xg4 = (const float4*)(x + ((size_t)(b * CC) * HH + y) * WW + x0);
        const int cstride4 = (HH * WW) / 4;
        #pragma unroll
        for (int idx = tid; idx < CC * TQ; idx += NTHREADS) {
            int c = idx / TQ;
            int q = idx - c * TQ;
            xs4[c * TQ + q] = xg4[(size_t)c * cstride4 + q];
        }
    }
    __syncthreads();

    // ---------------- Phase 2: hs_t[px][o] = sum_c rw[o][c]*xs[c][px] ------
    // warp w -> o in {4w..4w+3}; lane = px. Weights lane-uniform; xs read once.
    if (lane < TW) {
        const int o0 = warp * 4;
        const float4* w0 = (const float4*)(rw + (o0 + 0) * CC);
        const float4* w1 = (const float4*)(rw + (o0 + 1) * CC);
        const float4* w2 = (const float4*)(rw + (o0 + 2) * CC);
        const float4* w3 = (const float4*)(rw + (o0 + 3) * CC);
        float a0 = 0.f, a1 = 0.f, a2 = 0.f, a3 = 0.f;
        #pragma unroll 4
        for (int kq = 0; kq < CC / 4; kq++) {
            float4 wa = w0[kq], wb = w1[kq], wc = w2[kq], wd = w3[kq];
            float v0 = xs[(4 * kq + 0) * TW + lane];
            float v1 = xs[(4 * kq + 1) * TW + lane];
            float v2 = xs[(4 * kq + 2) * TW + lane];
            float v3 = xs[(4 * kq + 3) * TW + lane];
            a0 += wa.x * v0 + wa.y * v1 + wa.z * v2 + wa.w * v3;
            a1 += wb.x * v0 + wb.y * v1 + wb.z * v2 + wb.w * v3;
            a2 += wc.x * v0 + wc.y * v1 + wc.z * v2 + wc.w * v3;
            a3 += wd.x * v0 + wd.y * v1 + wd.z * v2 + wd.w * v3;
        }
        float4 r = make_float4(a0 + rb[o0 + 0], a1 + rb[o0 + 1],
                               a2 + rb[o0 + 2], a3 + rb[o0 + 3]);
        hs4[lane * HSTR4 + warp] = r;   // hs_t[px][o0..o0+3]
    }
    __syncthreads();

    // ---------------- Phase 3: ks[o][px] = sum_k sw[o][k]*h[k][px] + sb[o] -
    // 7o x 7px register tile; 112 oq x 4 pq = 448 tasks (1/thread).
    if (tid < 448) {
        const int oq  = tid >> 2;
        const int pq  = tid & 3;
        const int o0  = oq * 7;
        const int px0 = pq * 7;

        float acc[7][7];
        #pragma unroll
        for (int j = 0; j < 7; j++)
            #pragma unroll
            for (int i = 0; i < 7; i++) acc[j][i] = 0.f;

        #pragma unroll 4
        for (int kq = 0; kq < CR / 4; kq++) {
            float4 v[7];
            #pragma unroll
            for (int i = 0; i < 7; i++)
                v[i] = hs4[(px0 + i) * HSTR4 + kq];     // hs_t[px][k..k+3]
            #pragma unroll
            for (int j = 0; j < 7; j++) {
                float4 w = *(const float4*)(sw + (o0 + j) * CR + 4 * kq);
                #pragma unroll
                for (int i = 0; i < 7; i++)
                    acc[j][i] += w.x * v[i].x + w.y * v[i].y
                               + w.z * v[i].z + w.w * v[i].w;
            }
        }
        #pragma unroll
        for (int j = 0; j < 7; j++) {
            float bias = sb[o0 + j];
            float* krow = ks + (o0 + j) * TW + px0;
            #pragma unroll
            for (int i = 0; i < 7; i++) krow[i] = acc[j][i] + bias;
        }
    }
    __syncthreads();

    // ---------------- Phase 4: involution apply ----------------------------
    // warp g handles group g; lane = px. kern in 49 regs, x window in smem.
    float kr[KK];
    if (lane < TW) {
        const float* kb = ks + warp * KK * TW + lane;
        #pragma unroll
        for (int t = 0; t < KK; t++) kr[t] = kb[t * TW];
    }

    #pragma unroll
    for (int half = 0; half < 2; half++) {
        // fill xw: 128 channels x 7 rows x 9 quads, zero-padded borders
        {
            float4* xw4 = (float4*)xw;
            const float4 zero4 = make_float4(0.f, 0.f, 0.f, 0.f);
            for (int idx = tid; idx < XWC * KF * (XWW / 4); idx += NTHREADS) {
                int cl = idx / (KF * (XWW / 4));
                int rq = idx - cl * (KF * (XWW / 4));
                int r  = rq / (XWW / 4);
                int q  = rq - r * (XWW / 4);
                int g  = cl >> 3;
                int ci = cl & 7;
                int c  = g * CPG + half * 8 + ci;
                int yy = y + r - PAD;
                int col0 = x0 - 4 + q * 4;
                float4 v = zero4;
                if ((unsigned)yy < HH && (unsigned)col0 < WW)
                    v = *(const float4*)(x + ((size_t)(b * CC + c) * HH + yy) * WW + col0);
                xw4[idx] = v;
            }
        }
        __syncthreads();

        if (lane < TW) {
            const int g = warp;
            #pragma unroll 1
            for (int ci = 0; ci < 8; ci++) {
                const float* wrow = xw + ((g * 8 + ci) * KF) * XWW + lane + 1;
                float a0 = 0.f, a1 = 0.f;
                #pragma unroll
                for (int r = 0; r < KF; r++) {
                    #pragma unroll
                    for (int kw = 0; kw < KF; kw++) {
                        float v = wrow[r * XWW + kw];
                        if (kw & 1) a1 += kr[r * KF + kw] * v;
                        else        a0 += kr[r * KF + kw] * v;
                    }
                }
                const int c = g * CPG + half * 8 + ci;
                out[((size_t)(b * CC + c) * HH + y) * WW + x0 + lane] = a0 + a1;
            }
        }
        __syncthreads();   // WAR before next fill overwrites xw
    }
}

extern "C" void kernel_launch(void* const* d_in, const int* in_sizes, int n_in,
                              void* d_out, int out_size)
{
    const float* x  = (const float*)d_in[0];  // (4,256,56,56)
    const float* rw = (const float*)d_in[1];  // (64,256)
    const float* rb = (const float*)d_in[2];  // (64,)
    const float* sw = (const float*)d_in[3];  // (784,64)
    const float* sb = (const float*)d_in[4];  // (784,)
    float* out = (float*)d_out;               // (4,256,56,56)

    const int smem_bytes = SMEM_FLOATS * (int)sizeof(float);  // 216832
    cudaFuncSetAttribute(inv_fused_kernel,
                         cudaFuncAttributeMaxDynamicSharedMemorySize, smem_bytes);

    dim3 grid(WW / TW, HH, BB);   // (2, 56, 4) = 448 blocks
    inv_fused_kernel<<<grid, NTHREADS, smem_bytes>>>(x, rw, rb, sw, sb, out);
}

// round 4
// speedup vs baseline: 1.5044x; 1.2000x over previous
#include <cuda_runtime.h>

// involution: B=4, C=256, G=16, K=7, S=1, P=3, R=4, H=W=56
#define BB   4
#define CC   256
#define GG   16
#define CPG  16      // C/G
#define KF   7
#define PAD  3
#define HH   56
#define WW   56
#define CR   64      // C/R
#define KK   49      // K*K
#define KKG  784     // K*K*G
#define TW   28      // pixel tile width (half a row)
#define TQ   (TW/4)
#define NTHREADS 256

#define HSTR  76              // hs_t row stride (conflict-free, 4-aligned)
#define HSTR4 (HSTR/4)        // 19

#define XSC   128             // channels per xs half
#define XWC   16              // channels per P4 chunk
#define XWW   36              // padded window width
#define KS_FLOATS  (KKG * TW)                 // 21952
#define XS_FLOATS  (XSC * TW)                 // 3584
#define HS_FLOATS  (TW * HSTR)                // 2128
#define REG_FLOATS (XS_FLOATS + HS_FLOATS)    // 5712 (>= XWC*KF*XWW = 4032)
#define SMEM_FLOATS (KS_FLOATS + REG_FLOATS)  // 27664 floats = 110656 B

__global__ __launch_bounds__(NTHREADS, 2)
void inv_fused_kernel(const float* __restrict__ x,
                      const float* __restrict__ rw,   // [CR][C]
                      const float* __restrict__ rb,   // [CR]
                      const float* __restrict__ sw,   // [KKG][CR]
                      const float* __restrict__ sb,   // [KKG]
                      float* __restrict__ out)
{
    extern __shared__ float smem[];
    float* ks = smem;                    // [KKG][TW] 87.8 KB (rw parked here pre-P3)
    float* xs = smem + KS_FLOATS;        // [XSC][TW]
    float* hs = xs + XS_FLOATS;          // hs_t [TW][HSTR]
    float* xw = smem + KS_FLOATS;        // [XWC][KF][XWW] (P4 only, overlays xs/hs)
    float4* xs4  = (float4*)xs;
    float4* hs4  = (float4*)hs;
    float4* rws4 = (float4*)ks;          // staged rw, float4 view

    const int x0   = blockIdx.x * TW;
    const int y    = blockIdx.y;
    const int b    = blockIdx.z;
    const int tid  = threadIdx.x;
    const int warp = tid >> 5;           // 0..7
    const int lane = tid & 31;

    // ---------------- Phase 0: stage rw[64][256] into smem (ks area) -------
    {
        const float4* rwg4 = (const float4*)rw;
        #pragma unroll
        for (int i = tid; i < (CR * CC) / 4; i += NTHREADS)
            rws4[i] = rwg4[i];
    }

    // ---------------- Phase 1+2: hs_t[px][o] = sum_c rw[o][c]*x[c][px] -----
    // warp w -> o rows 8w..8w+7; xs streamed in two 128-channel halves.
    {
        float acc[8];
        #pragma unroll
        for (int j = 0; j < 8; j++) acc[j] = 0.f;
        const int o0 = warp * 8;

        #pragma unroll
        for (int half = 0; half < 2; half++) {
            if (half) __syncthreads();   // WAR on xs
            // load xs half: 128 ch x 7 quads
            {
                const float4* xg4 = (const float4*)
                    (x + ((size_t)(b * CC + half * XSC) * HH + y) * WW + x0);
                const int cstride4 = (HH * WW) / 4;
                #pragma unroll
                for (int idx = tid; idx < XSC * TQ; idx += NTHREADS) {
                    int c = idx / TQ;
                    int q = idx - c * TQ;
                    xs4[c * TQ + q] = xg4[(size_t)c * cstride4 + q];
                }
            }
            __syncthreads();

            if (lane < TW) {
                #pragma unroll 2
                for (int kq = 0; kq < XSC / 4; kq++) {
                    float v0 = xs[(4 * kq + 0) * TW + lane];
                    float v1 = xs[(4 * kq + 1) * TW + lane];
                    float v2 = xs[(4 * kq + 2) * TW + lane];
                    float v3 = xs[(4 * kq + 3) * TW + lane];
                    #pragma unroll
                    for (int j = 0; j < 8; j++) {
                        float4 w = rws4[(o0 + j) * (CC / 4) + half * (XSC / 4) + kq];
                        acc[j] += w.x * v0 + w.y * v1 + w.z * v2 + w.w * v3;
                    }
                }
            }
        }
        if (lane < TW) {
            #pragma unroll
            for (int j = 0; j < 8; j++)
                hs[lane * HSTR + o0 + j] = acc[j] + rb[o0 + j];
        }
    }
    __syncthreads();   // hs ready; all rw-in-ks reads done (P3 overwrites ks)

    // ---------------- Phase 3: ks[o][px] = sum_k sw[o][k]*h[k][px] + sb[o] -
    // 7o x 7px register tile; 448 tasks over 2 rounds.
    #pragma unroll
    for (int t = tid; t < 448; t += NTHREADS) {
        const int oq  = t >> 2;
        const int pq  = t & 3;
        const int o0  = oq * 7;
        const int px0 = pq * 7;

        float acc[7][7];
        #pragma unroll
        for (int j = 0; j < 7; j++)
            #pragma unroll
            for (int i = 0; i < 7; i++) acc[j][i] = 0.f;

        #pragma unroll 4
        for (int kq = 0; kq < CR / 4; kq++) {
            float4 v[7];
            #pragma unroll
            for (int i = 0; i < 7; i++)
                v[i] = hs4[(px0 + i) * HSTR4 + kq];
            #pragma unroll
            for (int j = 0; j < 7; j++) {
                float4 w = *(const float4*)(sw + (o0 + j) * CR + 4 * kq);
                #pragma unroll
                for (int i = 0; i < 7; i++)
                    acc[j][i] += w.x * v[i].x + w.y * v[i].y
                               + w.z * v[i].z + w.w * v[i].w;
            }
        }
        #pragma unroll
        for (int j = 0; j < 7; j++) {
            float bias = sb[o0 + j];
            float* krow = ks + (o0 + j) * TW + px0;
            #pragma unroll
            for (int i = 0; i < 7; i++) krow[i] = acc[j][i] + bias;
        }
    }
    __syncthreads();   // ks complete (also covers xs/hs death before xw fill)

    // ---------------- Phase 4: involution apply ----------------------------
    // subround s: warp w owns group g=8s+w, kern in 49 regs.
    // channels streamed 16 at a time (2 per group), window zero-padded in smem.
    #pragma unroll
    for (int s = 0; s < 2; s++) {
        const int g = 8 * s + warp;
        float kr[KK];
        if (lane < TW) {
            const float* kb = ks + g * KK * TW + lane;
            #pragma unroll
            for (int t = 0; t < KK; t++) kr[t] = kb[t * TW];
        }

        #pragma unroll 1
        for (int j = 0; j < 8; j++) {
            __syncthreads();   // WAR on xw (first iter: after kr loads too — ks only read)
            // fill chunk: 16 channels (slot = 2*wl+ci -> c = (8s+wl)*16 + 2j+ci)
            {
                float4* xw4 = (float4*)xw;
                const float4 zero4 = make_float4(0.f, 0.f, 0.f, 0.f);
                #pragma unroll
                for (int idx = tid; idx < XWC * KF * (XWW / 4); idx += NTHREADS) {
                    int slot = idx / (KF * (XWW / 4));
                    int rq   = idx - slot * (KF * (XWW / 4));
                    int r    = rq / (XWW / 4);
                    int q    = rq - r * (XWW / 4);
                    int wl   = slot >> 1;
                    int ci   = slot & 1;
                    int c    = (8 * s + wl) * CPG + 2 * j + ci;
                    int yy   = y + r - PAD;
                    int col0 = x0 - 4 + q * 4;
                    float4 v = zero4;
                    if ((unsigned)yy < HH && (unsigned)col0 < WW)
                        v = *(const float4*)(x + ((size_t)(b * CC + c) * HH + yy) * WW + col0);
                    xw4[idx] = v;
                }
            }
            __syncthreads();

            if (lane < TW) {
                #pragma unroll
                for (int ci = 0; ci < 2; ci++) {
                    const float* wrow = xw + ((2 * warp + ci) * KF) * XWW + lane + 1;
                    float a0 = 0.f, a1 = 0.f;
                    #pragma unroll
                    for (int r = 0; r < KF; r++) {
                        #pragma unroll
                        for (int kw = 0; kw < KF; kw++) {
                            float v = wrow[r * XWW + kw];
                            if (kw & 1) a1 += kr[r * KF + kw] * v;
                            else        a0 += kr[r * KF + kw] * v;
                        }
                    }
                    const int c = g * CPG + 2 * j + ci;
                    out[((size_t)(b * CC + c) * HH + y) * WW + x0 + lane] = a0 + a1;
                }
            }
        }
        if (s == 0) __syncthreads();  // xw reads done before next subround's fills
    }
}

extern "C" void kernel_launch(void* const* d_in, const int* in_sizes, int n_in,
                              void* d_out, int out_size)
{
    const float* x  = (const float*)d_in[0];  // (4,256,56,56)
    const float* rw = (const float*)d_in[1];  // (64,256)
    const float* rb = (const float*)d_in[2];  // (64,)
    const float* sw = (const float*)d_in[3];  // (784,64)
    const float* sb = (const float*)d_in[4];  // (784,)
    float* out = (float*)d_out;               // (4,256,56,56)

    const int smem_bytes = SMEM_FLOATS * (int)sizeof(float);  // 110656
    cudaFuncSetAttribute(inv_fused_kernel,
                         cudaFuncAttributeMaxDynamicSharedMemorySize, smem_bytes);

    dim3 grid(WW / TW, HH, BB);   // (2, 56, 4) = 448 blocks
    inv_fused_kernel<<<grid, NTHREADS, smem_bytes>>>(x, rw, rb, sw, sb, out);
}